// round 1
// baseline (speedup 1.0000x reference)
#include <cuda_runtime.h>
#include <cstdint>

// ---------------- problem dims (hardcoded to this problem instance) -------
#define Bd 2
#define Td 2048
#define Cd 512
#define Hd 8
#define HSd 64
#define Ld 4
#define Vd 32000
#define NT (Bd*Td)        // 4096 rows
#define QKVW (3*Cd)       // 1536
#define FFW (4*Cd)        // 2048
#define TTd (Td*Td)       // 4194304

// ---------------- scratch (static device allocations: allowed) -----------
__device__ float g_x   [NT*Cd];
__device__ float g_h   [NT*Cd];
__device__ float g_qkv [NT*QKVW + 512];            // +pad: PV tile reads 128-wide on a 64-wide strip
__device__ float g_wei [Bd*Hd*Td*Td];              // 268 MB attention scores
__device__ float g_att [NT*Cd];
__device__ float g_ff1 [NT*FFW];
__device__ float g_ff2 [NT*Cd];
__device__ float g_wqkv[Ld*Cd*QKVW];               // packed [L][C][3C] qkv weights

// ---------------- embedding ----------------------------------------------
__global__ void embed_kernel(const int* __restrict__ idx,
                             const float* __restrict__ tok,
                             const float* __restrict__ pos,
                             float* __restrict__ out) {
    int r = blockIdx.x;            // 0..NT-1
    int t = r & (Td - 1);
    int token = idx[r];
    int c = threadIdx.x;           // 256 threads, 2 elems each
    const float* tp = tok + (size_t)token * Cd;
    const float* pp = pos + (size_t)t * Cd;
    float* op = out + (size_t)r * Cd;
    op[c]       = tp[c]       + pp[c];
    op[c + 256] = tp[c + 256] + pp[c + 256];
}

// ---------------- qkv weight pack: [H,C,HS] x3 -> [C, 3C] per layer ------
__global__ void pack_qkv_kernel(const float* __restrict__ wq,
                                const float* __restrict__ wk,
                                const float* __restrict__ wv,
                                float* __restrict__ out) {
    int i = blockIdx.x * 256 + threadIdx.x;
    const int total = Ld * Cd * QKVW;
    if (i >= total) return;
    int j = i % QKVW;
    int c = (i / QKVW) % Cd;
    int l = i / (QKVW * Cd);
    int which = j >> 9;            // 0=q,1=k,2=v
    int hj = j & 511;
    int h = hj >> 6;
    int d = hj & 63;
    const float* src = (which == 0) ? wq : (which == 1) ? wk : wv;
    out[i] = src[(((size_t)l * Hd + h) * Cd + c) * HSd + d];
}

// ---------------- layernorm (optionally out = add + LN(in)) --------------
template<bool ADD>
__global__ void ln_kernel(const float* __restrict__ in, float* __restrict__ out,
                          const float* __restrict__ gw, const float* __restrict__ bw,
                          const float* __restrict__ add) {
    int r = blockIdx.x;
    const float* x = in + (size_t)r * Cd;
    int tid = threadIdx.x;         // 256
    float v0 = x[tid], v1 = x[tid + 256];
    __shared__ float rs[256], rq[256];
    rs[tid] = v0 + v1;
    rq[tid] = v0 * v0 + v1 * v1;
    __syncthreads();
    #pragma unroll
    for (int off = 128; off > 0; off >>= 1) {
        if (tid < off) { rs[tid] += rs[tid + off]; rq[tid] += rq[tid + off]; }
        __syncthreads();
    }
    float mean = rs[0] * (1.0f / Cd);
    float var  = rq[0] * (1.0f / Cd) - mean * mean;
    float inv  = rsqrtf(var + 1e-5f);
    float o0 = (v0 - mean) * inv * gw[tid]       + bw[tid];
    float o1 = (v1 - mean) * inv * gw[tid + 256] + bw[tid + 256];
    if (ADD) {
        o0 += add[(size_t)r * Cd + tid];
        o1 += add[(size_t)r * Cd + tid + 256];
    }
    out[(size_t)r * Cd + tid]       = o0;
    out[(size_t)r * Cd + tid + 256] = o1;
}

// ---------------- causal softmax (in-place on g_wei) ----------------------
// Row (bh, t): softmax over s in [0, t]; zero-fill s in (t, 128-aligned end)
// so the PV GEMM (K limited to the diagonal 128-block) reads exact zeros.
__global__ void softmax_kernel(float* __restrict__ wei) {
    int t  = blockIdx.x;
    int bh = blockIdx.y;
    float* row = wei + (size_t)bh * TTd + (size_t)t * Td;
    int len = t + 1;
    int tid = threadIdx.x;         // 256
    __shared__ float sh[Td];
    __shared__ float red[256];

    float mx = -1e30f;
    for (int i = tid; i < len; i += 256) mx = fmaxf(mx, row[i]);
    red[tid] = mx; __syncthreads();
    #pragma unroll
    for (int off = 128; off > 0; off >>= 1) {
        if (tid < off) red[tid] = fmaxf(red[tid], red[tid + off]);
        __syncthreads();
    }
    mx = red[0]; __syncthreads();

    float sum = 0.f;
    for (int i = tid; i < len; i += 256) {
        float e = __expf(row[i] - mx);
        sh[i] = e;
        sum += e;
    }
    red[tid] = sum; __syncthreads();
    #pragma unroll
    for (int off = 128; off > 0; off >>= 1) {
        if (tid < off) red[tid] += red[tid + off];
        __syncthreads();
    }
    float invs = 1.0f / red[0];

    for (int i = tid; i < len; i += 256) row[i] = sh[i] * invs;
    int zend = ((t >> 7) + 1) << 7;       // next multiple of 128
    for (int i = len + tid; i < zend; i += 256) row[i] = 0.0f;
}

// ---------------- templated SGEMM ----------------------------------------
// C[M,N] = A[M,K] * B(+epilogue).  BT: B is [N,K] row-major (use B^T).
// CAUSAL: skip tiles strictly above the diagonal (M==N square, 128 tiles).
// TRILIM: limit K to row0+128 (A's columns are zero beyond the diagonal blk).
// Requirements (all satisfied by our shapes): M%128==0, K%8==0, strips of 8
// output columns are either fully <N or fully >=N (N%64==0), float4-aligned
// lda/ldb/ldc and base offsets (multiples of 4 floats).
#define BM 128
#define BN 128
#define BKt 8
#define TM 8
#define TN 8

template<bool BT, bool BIAS, bool RELU, bool RESID, bool CAUSAL, bool TRILIM>
__global__ __launch_bounds__(256)
void sgemm_kernel(const float* __restrict__ A, const float* __restrict__ B,
                  float* __restrict__ C,
                  const float* __restrict__ bias, const float* __restrict__ resid,
                  int M, int N, int K, int lda, int ldb, int ldc,
                  long long sAo, long long sAi,
                  long long sBo, long long sBi,
                  long long sCo, long long sCi, int nInner) {
    int row0 = blockIdx.y * BM;
    int col0 = blockIdx.x * BN;
    if (CAUSAL && col0 > row0) return;

    int bo = blockIdx.z / nInner;
    int bi = blockIdx.z % nInner;
    A += bo * sAo + bi * sAi;
    B += bo * sBo + bi * sBi;
    C += bo * sCo + bi * sCi;
    const float* Rp = resid;
    if (RESID) Rp += bo * sCo + bi * sCi;

    __shared__ float As[BKt][BM];
    __shared__ float Bs[BKt][BN];

    int tid = threadIdx.x;
    int tx = tid & 15;             // 0..15  (N strip)
    int ty = tid >> 4;             // 0..15  (M strip)

    // loader indices: 128 rows x 8 cols tiles, one float4 per thread
    int arow = tid >> 1;
    int acol = (tid & 1) << 2;
    // normal-B loader: 8 rows x 128 cols
    int brow = tid >> 5;
    int bcol = (tid & 31) << 2;

    float acc[TM][TN];
    #pragma unroll
    for (int i = 0; i < TM; i++)
        #pragma unroll
        for (int j = 0; j < TN; j++) acc[i][j] = 0.0f;

    int Keff = K;
    if (TRILIM) Keff = min(K, row0 + BM);

    for (int k0 = 0; k0 < Keff; k0 += BKt) {
        float4 av = *(const float4*)&A[(size_t)(row0 + arow) * lda + k0 + acol];
        As[acol + 0][arow] = av.x;
        As[acol + 1][arow] = av.y;
        As[acol + 2][arow] = av.z;
        As[acol + 3][arow] = av.w;
        if (BT) {
            float4 bv = *(const float4*)&B[(size_t)(col0 + arow) * ldb + k0 + acol];
            Bs[acol + 0][arow] = bv.x;
            Bs[acol + 1][arow] = bv.y;
            Bs[acol + 2][arow] = bv.z;
            Bs[acol + 3][arow] = bv.w;
        } else {
            float4 bv = *(const float4*)&B[(size_t)(k0 + brow) * ldb + col0 + bcol];
            *(float4*)&Bs[brow][bcol] = bv;
        }
        __syncthreads();

        #pragma unroll
        for (int kk = 0; kk < BKt; kk++) {
            float a[TM], bb[TN];
            #pragma unroll
            for (int i = 0; i < TM; i++) a[i] = As[kk][ty * TM + i];
            #pragma unroll
            for (int j = 0; j < TN; j++) bb[j] = Bs[kk][tx * TN + j];
            #pragma unroll
            for (int i = 0; i < TM; i++)
                #pragma unroll
                for (int j = 0; j < TN; j++)
                    acc[i][j] += a[i] * bb[j];
        }
        __syncthreads();
    }

    int colbase = col0 + tx * TN;
    if (colbase >= N) return;      // partial-N tiles (PV: N=64)

    float4 bv0 = make_float4(0, 0, 0, 0), bv1 = make_float4(0, 0, 0, 0);
    if (BIAS) {
        bv0 = *(const float4*)&bias[colbase];
        bv1 = *(const float4*)&bias[colbase + 4];
    }
    #pragma unroll
    for (int i = 0; i < TM; i++) {
        int row = row0 + ty * TM + i;
        float* cp = &C[(size_t)row * ldc + colbase];
        float4 r0 = make_float4(acc[i][0], acc[i][1], acc[i][2], acc[i][3]);
        float4 r1 = make_float4(acc[i][4], acc[i][5], acc[i][6], acc[i][7]);
        if (BIAS) {
            r0.x += bv0.x; r0.y += bv0.y; r0.z += bv0.z; r0.w += bv0.w;
            r1.x += bv1.x; r1.y += bv1.y; r1.z += bv1.z; r1.w += bv1.w;
        }
        if (RESID) {
            float4 d0 = *(const float4*)&Rp[(size_t)row * ldc + colbase];
            float4 d1 = *(const float4*)&Rp[(size_t)row * ldc + colbase + 4];
            r0.x += d0.x; r0.y += d0.y; r0.z += d0.z; r0.w += d0.w;
            r1.x += d1.x; r1.y += d1.y; r1.z += d1.z; r1.w += d1.w;
        }
        if (RELU) {
            r0.x = fmaxf(r0.x, 0.f); r0.y = fmaxf(r0.y, 0.f);
            r0.z = fmaxf(r0.z, 0.f); r0.w = fmaxf(r0.w, 0.f);
            r1.x = fmaxf(r1.x, 0.f); r1.y = fmaxf(r1.y, 0.f);
            r1.z = fmaxf(r1.z, 0.f); r1.w = fmaxf(r1.w, 0.f);
        }
        *(float4*)cp = r0;
        *(float4*)(cp + 4) = r1;
    }
}

// ---------------- host orchestration --------------------------------------
extern "C" void kernel_launch(void* const* d_in, const int* in_sizes, int n_in,
                              void* d_out, int out_size) {
    const int*   idx     = (const int*)  d_in[0];
    const float* tok_emb = (const float*)d_in[1];
    const float* pos_emb = (const float*)d_in[2];
    const float* ln1_g   = (const float*)d_in[3];
    const float* ln1_b   = (const float*)d_in[4];
    const float* wq      = (const float*)d_in[5];
    const float* wk      = (const float*)d_in[6];
    const float* wv      = (const float*)d_in[7];
    const float* proj_w  = (const float*)d_in[8];
    const float* proj_b  = (const float*)d_in[9];
    const float* ln2_g   = (const float*)d_in[10];
    const float* ln2_b   = (const float*)d_in[11];
    const float* ff_w1   = (const float*)d_in[12];
    const float* ff_b1   = (const float*)d_in[13];
    const float* ff_w2   = (const float*)d_in[14];
    const float* ff_b2   = (const float*)d_in[15];
    const float* ffln_g  = (const float*)d_in[16];
    const float* ffln_b  = (const float*)d_in[17];
    const float* lm_w    = (const float*)d_in[18];
    const float* lm_b    = (const float*)d_in[19];
    float* out = (float*)d_out;

    float *x, *h, *qkv, *wei, *att, *ff1, *ff2, *wqkv;
    cudaGetSymbolAddress((void**)&x,    g_x);
    cudaGetSymbolAddress((void**)&h,    g_h);
    cudaGetSymbolAddress((void**)&qkv,  g_qkv);
    cudaGetSymbolAddress((void**)&wei,  g_wei);
    cudaGetSymbolAddress((void**)&att,  g_att);
    cudaGetSymbolAddress((void**)&ff1,  g_ff1);
    cudaGetSymbolAddress((void**)&ff2,  g_ff2);
    cudaGetSymbolAddress((void**)&wqkv, g_wqkv);

    // embedding + weight packing
    embed_kernel<<<NT, 256>>>(idx, tok_emb, pos_emb, x);
    {
        const int total = Ld * Cd * QKVW;
        pack_qkv_kernel<<<(total + 255) / 256, 256>>>(wq, wk, wv, wqkv);
    }

    for (int l = 0; l < Ld; l++) {
        // LN1
        ln_kernel<false><<<NT, 256>>>(x, h, ln1_g + l * Cd, ln1_b + l * Cd, nullptr);

        // fused QKV GEMM: [4096,512] x [512,1536] -> qkv [4096,1536] ([b,t][q|k|v])
        sgemm_kernel<false, false, false, false, false, false>
            <<<dim3(QKVW / BN, NT / BM, 1), 256>>>(
            h, wqkv + (size_t)l * Cd * QKVW, qkv, nullptr, nullptr,
            NT, QKVW, Cd, Cd, QKVW, QKVW,
            0, 0, 0, 0, 0, 0, 1);

        // scores: wei[b,h,t,s] = Q . K  (BT, causal tile-skip), batched (b,h)
        sgemm_kernel<true, false, false, false, true, false>
            <<<dim3(Td / BN, Td / BM, Bd * Hd), 256>>>(
            qkv /*Q at col 0*/, qkv + Cd /*K at col 512*/, wei, nullptr, nullptr,
            Td, Td, HSd, QKVW, QKVW, Td,
            (long long)Td * QKVW, HSd,
            (long long)Td * QKVW, HSd,
            (long long)Hd * TTd, (long long)TTd, Hd);

        // causal softmax in-place
        softmax_kernel<<<dim3(Td, Bd * Hd), 256>>>(wei);

        // PV: att[b,t,h,d] = wei . V   (K limited to diagonal block)
        sgemm_kernel<false, false, false, false, false, true>
            <<<dim3(1, Td / BM, Bd * Hd), 256>>>(
            wei, qkv + 2 * Cd /*V at col 1024*/, att, nullptr, nullptr,
            Td, HSd, Td, Td, QKVW, Cd,
            (long long)Hd * TTd, (long long)TTd,
            (long long)Td * QKVW, HSd,
            (long long)Td * Cd, HSd, Hd);

        // proj: x = x + att @ proj_w^T + proj_b   (BT + bias + residual)
        sgemm_kernel<true, true, false, true, false, false>
            <<<dim3(Cd / BN, NT / BM, 1), 256>>>(
            att, proj_w + (size_t)l * Cd * Cd, x,
            proj_b + l * Cd, x,
            NT, Cd, Cd, Cd, Cd, Cd,
            0, 0, 0, 0, 0, 0, 1);

        // LN2
        ln_kernel<false><<<NT, 256>>>(x, h, ln2_g + l * Cd, ln2_b + l * Cd, nullptr);

        // FF1: relu(h @ ff_w1 + b1) -> ff1 [4096,2048]
        sgemm_kernel<false, true, true, false, false, false>
            <<<dim3(FFW / BN, NT / BM, 1), 256>>>(
            h, ff_w1 + (size_t)l * Cd * FFW, ff1,
            ff_b1 + l * FFW, nullptr,
            NT, FFW, Cd, Cd, FFW, FFW,
            0, 0, 0, 0, 0, 0, 1);

        // FF2: ff1 @ ff_w2 + b2 -> ff2 [4096,512]
        sgemm_kernel<false, true, false, false, false, false>
            <<<dim3(Cd / BN, NT / BM, 1), 256>>>(
            ff1, ff_w2 + (size_t)l * FFW * Cd, ff2,
            ff_b2 + l * Cd, nullptr,
            NT, Cd, FFW, FFW, Cd, Cd,
            0, 0, 0, 0, 0, 0, 1);

        // x = x + LN(ff2)
        ln_kernel<true><<<NT, 256>>>(ff2, x, ffln_g + l * Cd, ffln_b + l * Cd, x);
    }

    // LM head: logits = x @ lm_w + lm_b -> d_out [4096, 32000]
    sgemm_kernel<false, true, false, false, false, false>
        <<<dim3(Vd / BN, NT / BM, 1), 256>>>(
        x, lm_w, out, lm_b, nullptr,
        NT, Vd, Cd, Cd, Vd, Vd,
        0, 0, 0, 0, 0, 0, 1);
}

// round 2
// speedup vs baseline: 1.0004x; 1.0004x over previous
#include <cuda_runtime.h>
#include <cstdint>

// ---------------- problem dims (hardcoded to this problem instance) -------
#define Bd 2
#define Td 2048
#define Cd 512
#define Hd 8
#define HSd 64
#define Ld 4
#define Vd 32000
#define NT (Bd*Td)        // 4096 rows
#define QKVW (3*Cd)       // 1536
#define FFW (4*Cd)        // 2048
#define TTd (Td*Td)       // 4194304

// ---------------- scratch (static device allocations: allowed) -----------
__device__ float g_x   [NT*Cd];
__device__ float g_h   [NT*Cd];
__device__ float g_qkv [NT*QKVW + 512];            // +pad: PV tile reads 128-wide on a 64-wide strip
__device__ float g_wei [Bd*Hd*Td*Td];              // 268 MB attention scores
__device__ float g_att [NT*Cd];
__device__ float g_ff1 [NT*FFW];
__device__ float g_ff2 [NT*Cd];
__device__ float g_wqkv[Ld*Cd*QKVW];               // packed [L][C][3C] qkv weights

// ---------------- embedding ----------------------------------------------
__global__ void embed_kernel(const int* __restrict__ idx,
                             const float* __restrict__ tok,
                             const float* __restrict__ pos,
                             float* __restrict__ out) {
    int r = blockIdx.x;            // 0..NT-1
    int t = r & (Td - 1);
    int token = idx[r];
    int c = threadIdx.x;           // 256 threads, 2 elems each
    const float* tp = tok + (size_t)token * Cd;
    const float* pp = pos + (size_t)t * Cd;
    float* op = out + (size_t)r * Cd;
    op[c]       = tp[c]       + pp[c];
    op[c + 256] = tp[c + 256] + pp[c + 256];
}

// ---------------- qkv weight pack: [H,C,HS] x3 -> [C, 3C] per layer ------
__global__ void pack_qkv_kernel(const float* __restrict__ wq,
                                const float* __restrict__ wk,
                                const float* __restrict__ wv,
                                float* __restrict__ out) {
    int i = blockIdx.x * 256 + threadIdx.x;
    const int total = Ld * Cd * QKVW;
    if (i >= total) return;
    int j = i % QKVW;
    int c = (i / QKVW) % Cd;
    int l = i / (QKVW * Cd);
    int which = j >> 9;            // 0=q,1=k,2=v
    int hj = j & 511;
    int h = hj >> 6;
    int d = hj & 63;
    const float* src = (which == 0) ? wq : (which == 1) ? wk : wv;
    out[i] = src[(((size_t)l * Hd + h) * Cd + c) * HSd + d];
}

// ---------------- layernorm (optionally out = add + LN(in)) --------------
template<bool ADD>
__global__ void ln_kernel(const float* __restrict__ in, float* __restrict__ out,
                          const float* __restrict__ gw, const float* __restrict__ bw,
                          const float* __restrict__ add) {
    int r = blockIdx.x;
    const float* x = in + (size_t)r * Cd;
    int tid = threadIdx.x;         // 256
    float v0 = x[tid], v1 = x[tid + 256];
    __shared__ float rs[256], rq[256];
    rs[tid] = v0 + v1;
    rq[tid] = v0 * v0 + v1 * v1;
    __syncthreads();
    #pragma unroll
    for (int off = 128; off > 0; off >>= 1) {
        if (tid < off) { rs[tid] += rs[tid + off]; rq[tid] += rq[tid + off]; }
        __syncthreads();
    }
    float mean = rs[0] * (1.0f / Cd);
    float var  = rq[0] * (1.0f / Cd) - mean * mean;
    float inv  = rsqrtf(var + 1e-5f);
    float o0 = (v0 - mean) * inv * gw[tid]       + bw[tid];
    float o1 = (v1 - mean) * inv * gw[tid + 256] + bw[tid + 256];
    if (ADD) {
        o0 += add[(size_t)r * Cd + tid];
        o1 += add[(size_t)r * Cd + tid + 256];
    }
    out[(size_t)r * Cd + tid]       = o0;
    out[(size_t)r * Cd + tid + 256] = o1;
}

// ---------------- causal softmax (in-place on g_wei) ----------------------
// Row (bh, t): softmax over s in [0, t]; zero-fill s in (t, 128-aligned end)
// so the PV GEMM (K limited to the diagonal 128-block) reads exact zeros.
__global__ void softmax_kernel(float* __restrict__ wei) {
    int t  = blockIdx.x;
    int bh = blockIdx.y;
    float* row = wei + (size_t)bh * TTd + (size_t)t * Td;
    int len = t + 1;
    int tid = threadIdx.x;         // 256
    __shared__ float sh[Td];
    __shared__ float red[256];

    float mx = -1e30f;
    for (int i = tid; i < len; i += 256) mx = fmaxf(mx, row[i]);
    red[tid] = mx; __syncthreads();
    #pragma unroll
    for (int off = 128; off > 0; off >>= 1) {
        if (tid < off) red[tid] = fmaxf(red[tid], red[tid + off]);
        __syncthreads();
    }
    mx = red[0]; __syncthreads();

    float sum = 0.f;
    for (int i = tid; i < len; i += 256) {
        float e = __expf(row[i] - mx);
        sh[i] = e;
        sum += e;
    }
    red[tid] = sum; __syncthreads();
    #pragma unroll
    for (int off = 128; off > 0; off >>= 1) {
        if (tid < off) red[tid] += red[tid + off];
        __syncthreads();
    }
    float invs = 1.0f / red[0];

    for (int i = tid; i < len; i += 256) row[i] = sh[i] * invs;
    int zend = ((t >> 7) + 1) << 7;       // next multiple of 128
    for (int i = len + tid; i < zend; i += 256) row[i] = 0.0f;
}

// ---------------- templated SGEMM ----------------------------------------
// C[M,N] = A[M,K] * B(+epilogue).  BT: B is [N,K] row-major (use B^T).
// CAUSAL: skip tiles strictly above the diagonal (M==N square, 128 tiles).
// TRILIM: limit K to row0+128 (A's columns are zero beyond the diagonal blk).
// Requirements (all satisfied by our shapes): M%128==0, K%8==0, strips of 8
// output columns are either fully <N or fully >=N (N%64==0), float4-aligned
// lda/ldb/ldc and base offsets (multiples of 4 floats).
#define BM 128
#define BN 128
#define BKt 8
#define TM 8
#define TN 8

template<bool BT, bool BIAS, bool RELU, bool RESID, bool CAUSAL, bool TRILIM>
__global__ __launch_bounds__(256)
void sgemm_kernel(const float* __restrict__ A, const float* __restrict__ B,
                  float* __restrict__ C,
                  const float* __restrict__ bias, const float* __restrict__ resid,
                  int M, int N, int K, int lda, int ldb, int ldc,
                  long long sAo, long long sAi,
                  long long sBo, long long sBi,
                  long long sCo, long long sCi, int nInner) {
    int row0 = blockIdx.y * BM;
    int col0 = blockIdx.x * BN;
    if (CAUSAL && col0 > row0) return;

    int bo = blockIdx.z / nInner;
    int bi = blockIdx.z % nInner;
    A += bo * sAo + bi * sAi;
    B += bo * sBo + bi * sBi;
    C += bo * sCo + bi * sCi;
    const float* Rp = resid;
    if (RESID) Rp += bo * sCo + bi * sCi;

    __shared__ float As[BKt][BM];
    __shared__ float Bs[BKt][BN];

    int tid = threadIdx.x;
    int tx = tid & 15;             // 0..15  (N strip)
    int ty = tid >> 4;             // 0..15  (M strip)

    // loader indices: 128 rows x 8 cols tiles, one float4 per thread
    int arow = tid >> 1;
    int acol = (tid & 1) << 2;
    // normal-B loader: 8 rows x 128 cols
    int brow = tid >> 5;
    int bcol = (tid & 31) << 2;

    float acc[TM][TN];
    #pragma unroll
    for (int i = 0; i < TM; i++)
        #pragma unroll
        for (int j = 0; j < TN; j++) acc[i][j] = 0.0f;

    int Keff = K;
    if (TRILIM) Keff = min(K, row0 + BM);

    for (int k0 = 0; k0 < Keff; k0 += BKt) {
        float4 av = *(const float4*)&A[(size_t)(row0 + arow) * lda + k0 + acol];
        As[acol + 0][arow] = av.x;
        As[acol + 1][arow] = av.y;
        As[acol + 2][arow] = av.z;
        As[acol + 3][arow] = av.w;
        if (BT) {
            float4 bv = *(const float4*)&B[(size_t)(col0 + arow) * ldb + k0 + acol];
            Bs[acol + 0][arow] = bv.x;
            Bs[acol + 1][arow] = bv.y;
            Bs[acol + 2][arow] = bv.z;
            Bs[acol + 3][arow] = bv.w;
        } else {
            float4 bv = *(const float4*)&B[(size_t)(k0 + brow) * ldb + col0 + bcol];
            *(float4*)&Bs[brow][bcol] = bv;
        }
        __syncthreads();

        #pragma unroll
        for (int kk = 0; kk < BKt; kk++) {
            float a[TM], bb[TN];
            #pragma unroll
            for (int i = 0; i < TM; i++) a[i] = As[kk][ty * TM + i];
            #pragma unroll
            for (int j = 0; j < TN; j++) bb[j] = Bs[kk][tx * TN + j];
            #pragma unroll
            for (int i = 0; i < TM; i++)
                #pragma unroll
                for (int j = 0; j < TN; j++)
                    acc[i][j] += a[i] * bb[j];
        }
        __syncthreads();
    }

    int colbase = col0 + tx * TN;
    if (colbase >= N) return;      // partial-N tiles (PV: N=64)

    float4 bv0 = make_float4(0, 0, 0, 0), bv1 = make_float4(0, 0, 0, 0);
    if (BIAS) {
        bv0 = *(const float4*)&bias[colbase];
        bv1 = *(const float4*)&bias[colbase + 4];
    }
    #pragma unroll
    for (int i = 0; i < TM; i++) {
        int row = row0 + ty * TM + i;
        float* cp = &C[(size_t)row * ldc + colbase];
        float4 r0 = make_float4(acc[i][0], acc[i][1], acc[i][2], acc[i][3]);
        float4 r1 = make_float4(acc[i][4], acc[i][5], acc[i][6], acc[i][7]);
        if (BIAS) {
            r0.x += bv0.x; r0.y += bv0.y; r0.z += bv0.z; r0.w += bv0.w;
            r1.x += bv1.x; r1.y += bv1.y; r1.z += bv1.z; r1.w += bv1.w;
        }
        if (RESID) {
            float4 d0 = *(const float4*)&Rp[(size_t)row * ldc + colbase];
            float4 d1 = *(const float4*)&Rp[(size_t)row * ldc + colbase + 4];
            r0.x += d0.x; r0.y += d0.y; r0.z += d0.z; r0.w += d0.w;
            r1.x += d1.x; r1.y += d1.y; r1.z += d1.z; r1.w += d1.w;
        }
        if (RELU) {
            r0.x = fmaxf(r0.x, 0.f); r0.y = fmaxf(r0.y, 0.f);
            r0.z = fmaxf(r0.z, 0.f); r0.w = fmaxf(r0.w, 0.f);
            r1.x = fmaxf(r1.x, 0.f); r1.y = fmaxf(r1.y, 0.f);
            r1.z = fmaxf(r1.z, 0.f); r1.w = fmaxf(r1.w, 0.f);
        }
        *(float4*)cp = r0;
        *(float4*)(cp + 4) = r1;
    }
}

// ---------------- host orchestration --------------------------------------
extern "C" void kernel_launch(void* const* d_in, const int* in_sizes, int n_in,
                              void* d_out, int out_size) {
    const int*   idx     = (const int*)  d_in[0];
    const float* tok_emb = (const float*)d_in[1];
    const float* pos_emb = (const float*)d_in[2];
    const float* ln1_g   = (const float*)d_in[3];
    const float* ln1_b   = (const float*)d_in[4];
    const float* wq      = (const float*)d_in[5];
    const float* wk      = (const float*)d_in[6];
    const float* wv      = (const float*)d_in[7];
    const float* proj_w  = (const float*)d_in[8];
    const float* proj_b  = (const float*)d_in[9];
    const float* ln2_g   = (const float*)d_in[10];
    const float* ln2_b   = (const float*)d_in[11];
    const float* ff_w1   = (const float*)d_in[12];
    const float* ff_b1   = (const float*)d_in[13];
    const float* ff_w2   = (const float*)d_in[14];
    const float* ff_b2   = (const float*)d_in[15];
    const float* ffln_g  = (const float*)d_in[16];
    const float* ffln_b  = (const float*)d_in[17];
    const float* lm_w    = (const float*)d_in[18];
    const float* lm_b    = (const float*)d_in[19];
    float* out = (float*)d_out;

    float *x, *h, *qkv, *wei, *att, *ff1, *ff2, *wqkv;
    cudaGetSymbolAddress((void**)&x,    g_x);
    cudaGetSymbolAddress((void**)&h,    g_h);
    cudaGetSymbolAddress((void**)&qkv,  g_qkv);
    cudaGetSymbolAddress((void**)&wei,  g_wei);
    cudaGetSymbolAddress((void**)&att,  g_att);
    cudaGetSymbolAddress((void**)&ff1,  g_ff1);
    cudaGetSymbolAddress((void**)&ff2,  g_ff2);
    cudaGetSymbolAddress((void**)&wqkv, g_wqkv);

    // embedding + weight packing
    embed_kernel<<<NT, 256>>>(idx, tok_emb, pos_emb, x);
    {
        const int total = Ld * Cd * QKVW;
        pack_qkv_kernel<<<(total + 255) / 256, 256>>>(wq, wk, wv, wqkv);
    }

    for (int l = 0; l < Ld; l++) {
        // LN1
        ln_kernel<false><<<NT, 256>>>(x, h, ln1_g + l * Cd, ln1_b + l * Cd, nullptr);

        // fused QKV GEMM: [4096,512] x [512,1536] -> qkv [4096,1536] ([b,t][q|k|v])
        sgemm_kernel<false, false, false, false, false, false>
            <<<dim3(QKVW / BN, NT / BM, 1), 256>>>(
            h, wqkv + (size_t)l * Cd * QKVW, qkv, nullptr, nullptr,
            NT, QKVW, Cd, Cd, QKVW, QKVW,
            0, 0, 0, 0, 0, 0, 1);

        // scores: wei[b,h,t,s] = Q . K  (BT, causal tile-skip), batched (b,h)
        sgemm_kernel<true, false, false, false, true, false>
            <<<dim3(Td / BN, Td / BM, Bd * Hd), 256>>>(
            qkv /*Q at col 0*/, qkv + Cd /*K at col 512*/, wei, nullptr, nullptr,
            Td, Td, HSd, QKVW, QKVW, Td,
            (long long)Td * QKVW, HSd,
            (long long)Td * QKVW, HSd,
            (long long)Hd * TTd, (long long)TTd, Hd);

        // causal softmax in-place
        softmax_kernel<<<dim3(Td, Bd * Hd), 256>>>(wei);

        // PV: att[b,t,h,d] = wei . V   (K limited to diagonal block)
        sgemm_kernel<false, false, false, false, false, true>
            <<<dim3(1, Td / BM, Bd * Hd), 256>>>(
            wei, qkv + 2 * Cd /*V at col 1024*/, att, nullptr, nullptr,
            Td, HSd, Td, Td, QKVW, Cd,
            (long long)Hd * TTd, (long long)TTd,
            (long long)Td * QKVW, HSd,
            (long long)Td * Cd, HSd, Hd);

        // proj: x = x + att @ proj_w^T + proj_b   (BT + bias + residual)
        sgemm_kernel<true, true, false, true, false, false>
            <<<dim3(Cd / BN, NT / BM, 1), 256>>>(
            att, proj_w + (size_t)l * Cd * Cd, x,
            proj_b + l * Cd, x,
            NT, Cd, Cd, Cd, Cd, Cd,
            0, 0, 0, 0, 0, 0, 1);

        // LN2
        ln_kernel<false><<<NT, 256>>>(x, h, ln2_g + l * Cd, ln2_b + l * Cd, nullptr);

        // FF1: relu(h @ ff_w1 + b1) -> ff1 [4096,2048]
        sgemm_kernel<false, true, true, false, false, false>
            <<<dim3(FFW / BN, NT / BM, 1), 256>>>(
            h, ff_w1 + (size_t)l * Cd * FFW, ff1,
            ff_b1 + l * FFW, nullptr,
            NT, FFW, Cd, Cd, FFW, FFW,
            0, 0, 0, 0, 0, 0, 1);

        // FF2: ff1 @ ff_w2 + b2 -> ff2 [4096,512]
        sgemm_kernel<false, true, false, false, false, false>
            <<<dim3(Cd / BN, NT / BM, 1), 256>>>(
            ff1, ff_w2 + (size_t)l * FFW * Cd, ff2,
            ff_b2 + l * Cd, nullptr,
            NT, Cd, FFW, FFW, Cd, Cd,
            0, 0, 0, 0, 0, 0, 1);

        // x = x + LN(ff2)
        ln_kernel<true><<<NT, 256>>>(ff2, x, ffln_g + l * Cd, ffln_b + l * Cd, x);
    }

    // LM head: logits = x @ lm_w + lm_b -> d_out [4096, 32000]
    sgemm_kernel<false, true, false, false, false, false>
        <<<dim3(Vd / BN, NT / BM, 1), 256>>>(
        x, lm_w, out, lm_b, nullptr,
        NT, Vd, Cd, Cd, Vd, Vd,
        0, 0, 0, 0, 0, 0, 1);
}